// round 1
// baseline (speedup 1.0000x reference)
#include <cuda_runtime.h>
#include <mma.h>

using namespace nvcuda;

#define DIM   768
#define NOUT  2304          // 3*DIM
#define RANK  16

// Folded effective weight: Weff[o][d] = Wqkv[o][d] + B_s[o'][r]*A_s[r][d]
__device__ float g_Weff[NOUT * DIM];

__global__ void fold_weights_kernel(const float* __restrict__ W,
                                    const float* __restrict__ Aq, const float* __restrict__ Bq,
                                    const float* __restrict__ Ak, const float* __restrict__ Bk,
                                    const float* __restrict__ Av, const float* __restrict__ Bv) {
    int idx = blockIdx.x * 256 + threadIdx.x;
    if (idx >= NOUT * DIM) return;
    int o = idx / DIM;
    int d = idx - o * DIM;
    int s = o / DIM;          // 0=q, 1=k, 2=v
    int op = o - s * DIM;     // row within slice
    const float* A = (s == 0) ? Aq : (s == 1) ? Ak : Av;   // [RANK, DIM]
    const float* B = (s == 0) ? Bq : (s == 1) ? Bk : Bv;   // [DIM, RANK]
    float acc = W[idx];
#pragma unroll
    for (int r = 0; r < RANK; r++) {
        acc += B[op * RANK + r] * A[r * DIM + d];
    }
    g_Weff[idx] = acc;
}

// GEMM: out[m][n] = sum_k x[m][k] * Weff[n][k] + bias[n]
// Block tile 128x64, BK=32, 8 warps (4x2), warp tile 32x32 (2x2 wmma 16x16x8 tf32)
#define BM 128
#define BN 64
#define BK 32
#define LDA 40   // BK + 8 pad (floats)
#define LDB 40

__global__ __launch_bounds__(256) void lora_qkv_gemm_kernel(
    const float* __restrict__ x,
    const float* __restrict__ bias,
    float* __restrict__ out,
    int M) {

    __shared__ float smem[8192];         // 32KB: A(5120)+B(2560) then reused as C(8192)
    __shared__ float bb[BN];
    float* As = smem;                     // [BM][LDA]
    float* Bs = smem + BM * LDA;          // [BN][LDB]

    const int tid = threadIdx.x;
    const int warp_id = tid >> 5;
    const int wm = warp_id & 3;           // 0..3  -> M offset wm*32
    const int wn = warp_id >> 2;          // 0..1  -> N offset wn*32

    const int gm0 = blockIdx.y * BM;
    const int gn0 = blockIdx.x * BN;

    if (tid < BN) bb[tid] = bias[gn0 + tid];

    wmma::fragment<wmma::accumulator, 16, 16, 8, float> acc[2][2];
#pragma unroll
    for (int i = 0; i < 2; i++)
#pragma unroll
        for (int j = 0; j < 2; j++)
            wmma::fill_fragment(acc[i][j], 0.0f);

    const float* xg = x + (size_t)gm0 * DIM;
    const float* wg = g_Weff + (size_t)gn0 * DIM;

    for (int k0 = 0; k0 < DIM; k0 += BK) {
        // Load A tile: 128 rows x 32 cols = 1024 float4, 4 per thread
#pragma unroll
        for (int i = 0; i < 4; i++) {
            int f4 = tid + i * 256;
            int row = f4 >> 3;            // /8 (8 float4 per row)
            int c4  = f4 & 7;
            float4 v = *reinterpret_cast<const float4*>(xg + (size_t)row * DIM + k0 + c4 * 4);
            *reinterpret_cast<float4*>(As + row * LDA + c4 * 4) = v;
        }
        // Load B tile: 64 rows x 32 cols = 512 float4, 2 per thread
#pragma unroll
        for (int i = 0; i < 2; i++) {
            int f4 = tid + i * 256;
            int row = f4 >> 3;
            int c4  = f4 & 7;
            float4 v = *reinterpret_cast<const float4*>(wg + (size_t)row * DIM + k0 + c4 * 4);
            *reinterpret_cast<float4*>(Bs + row * LDB + c4 * 4) = v;
        }
        __syncthreads();

#pragma unroll
        for (int kk = 0; kk < BK; kk += 8) {
            wmma::fragment<wmma::matrix_a, 16, 16, 8, wmma::precision::tf32, wmma::row_major> a[2];
            wmma::fragment<wmma::matrix_b, 16, 16, 8, wmma::precision::tf32, wmma::col_major> b[2];
#pragma unroll
            for (int i = 0; i < 2; i++) {
                wmma::load_matrix_sync(a[i], As + (wm * 32 + i * 16) * LDA + kk, LDA);
#pragma unroll
                for (int t = 0; t < a[i].num_elements; t++)
                    a[i].x[t] = wmma::__float_to_tf32(a[i].x[t]);
            }
#pragma unroll
            for (int j = 0; j < 2; j++) {
                wmma::load_matrix_sync(b[j], Bs + (wn * 32 + j * 16) * LDB + kk, LDB);
#pragma unroll
                for (int t = 0; t < b[j].num_elements; t++)
                    b[j].x[t] = wmma::__float_to_tf32(b[j].x[t]);
            }
#pragma unroll
            for (int i = 0; i < 2; i++)
#pragma unroll
                for (int j = 0; j < 2; j++)
                    wmma::mma_sync(acc[i][j], a[i], b[j], acc[i][j]);
        }
        __syncthreads();
    }

    // Epilogue: stage C in shared, add bias, write coalesced
    float* Cs = smem;                     // [BM][BN]
#pragma unroll
    for (int i = 0; i < 2; i++)
#pragma unroll
        for (int j = 0; j < 2; j++)
            wmma::store_matrix_sync(Cs + (wm * 32 + i * 16) * BN + wn * 32 + j * 16,
                                    acc[i][j], BN, wmma::mem_row_major);
    __syncthreads();

    float* og = out + (size_t)gm0 * NOUT + gn0;
#pragma unroll
    for (int i = 0; i < 32; i++) {
        int e = tid + i * 256;            // 0..8191
        int row = e >> 6;                 // /64
        int col = e & 63;
        og[(size_t)row * NOUT + col] = Cs[row * BN + col] + bb[col];
    }
}

extern "C" void kernel_launch(void* const* d_in, const int* in_sizes, int n_in,
                              void* d_out, int out_size) {
    const float* x    = (const float*)d_in[0];
    const float* Wqkv = (const float*)d_in[1];
    const float* bqkv = (const float*)d_in[2];
    const float* Aq   = (const float*)d_in[3];
    const float* Bq   = (const float*)d_in[4];
    const float* Ak   = (const float*)d_in[5];
    const float* Bk   = (const float*)d_in[6];
    const float* Av   = (const float*)d_in[7];
    const float* Bv   = (const float*)d_in[8];
    float* out = (float*)d_out;

    int M = in_sizes[0] / DIM;            // 32768 tokens

    // 1) Fold LoRA into effective weight
    int fold_elems = NOUT * DIM;
    fold_weights_kernel<<<(fold_elems + 255) / 256, 256>>>(Wqkv, Aq, Bq, Ak, Bk, Av, Bv);

    // 2) Single fused GEMM + bias
    dim3 grid(NOUT / BN, M / BM);         // 36 x 256
    lora_qkv_gemm_kernel<<<grid, 256>>>(x, bqkv, out, M);
}